// round 14
// baseline (speedup 1.0000x reference)
#include <cuda_runtime.h>
#include <cuda_fp16.h>
#include <cstdint>
#include <math.h>

#define BB   64
#define CC   64
#define HH   256
#define LL   64
#define PP   32
#define NREAL 2047
#define NN   2048
#define KTOT 1280   // 192 (conv1) + 768 (conv2) + 320 (mlp1)

// ---------------- global scratch ---------------------------------------------
__device__ __align__(16) __half g_xtH [(size_t)BB * NN * CC];
__device__ __align__(16) __half g_buf1[(size_t)BB * NN * HH];
__device__ __align__(16) __half g_buf2[(size_t)BB * NN * HH];
__device__ __align__(16) __half g_wpHi[HH * KTOT];
__device__ __align__(16) __half g_w2Hi[PP * HH];
__device__ __align__(16) __half g_w2Lo[PP * HH];
__device__ __align__(16) __half g_zs[BB * LL];        // z * sd(stage1), fp16
__device__ double g_stats[2][BB][2];
__device__ float  g_norm [2][BB][2];

// ---------------- smem layouts -------------------------------------------------
// gemm (M=128, KC=64, 2-stage): A st*18432 @0 ; B st*18432 @36864
#define GBA_OFF   0
#define GBB_OFF   36864
#define GBSIDX    73728
#define GBRS      75264
#define GBRSS     75328
#define GBBIAS    75392
#define GB_SMEM   75904
// mlp2
#define M2A_OFF  0
#define M2W_OFF  20480
#define M2_SMEM  54272

// ---------------- helpers -------------------------------------------------------
__device__ __forceinline__ uint32_t smem_u32(const void* p) {
    uint32_t a;
    asm("{ .reg .u64 t; cvta.to.shared.u64 t, %1; cvt.u32.u64 %0, t; }" : "=r"(a) : "l"(p));
    return a;
}
__device__ __forceinline__ void ldm4(uint32_t* r, uint32_t addr) {
    asm volatile("ldmatrix.sync.aligned.m8n8.x4.shared.b16 {%0,%1,%2,%3}, [%4];"
                 : "=r"(r[0]), "=r"(r[1]), "=r"(r[2]), "=r"(r[3]) : "r"(addr));
}
__device__ __forceinline__ void mma16816(float* c, const uint32_t* a, uint32_t b0, uint32_t b1) {
    asm volatile("mma.sync.aligned.m16n8k16.row.col.f32.f16.f16.f32 "
                 "{%0,%1,%2,%3}, {%4,%5,%6,%7}, {%8,%9}, {%0,%1,%2,%3};"
                 : "+f"(c[0]), "+f"(c[1]), "+f"(c[2]), "+f"(c[3])
                 : "r"(a[0]), "r"(a[1]), "r"(a[2]), "r"(a[3]), "r"(b0), "r"(b1));
}
__device__ __forceinline__ void cp16(uint32_t dst, const void* src) {
    asm volatile("cp.async.cg.shared.global [%0], [%1], 16;" :: "r"(dst), "l"(src));
}
#define CP_COMMIT() asm volatile("cp.async.commit_group;" ::: "memory")
#define CP_WAIT0()  asm volatile("cp.async.wait_group 0;"  ::: "memory")
__device__ __forceinline__ uint32_t pkh(__half a, __half b) {
    return (uint32_t)__half_as_ushort(a) | ((uint32_t)__half_as_ushort(b) << 16);
}
__device__ __forceinline__ uint32_t pkf(float a, float b) {
    return pkh(__float2half(a), __float2half(b));
}

// ---------------- init -----------------------------------------------------------
__global__ void k_init() {
    int t = blockIdx.x * blockDim.x + threadIdx.x;
    if (t < 2 * BB * 2) ((double*)g_stats)[t] = 0.0;
    for (int i = t; i < BB * HH; i += gridDim.x * blockDim.x) {
        int b = i >> 8, h = i & 255;
        g_buf1[(size_t)b * NN * HH + h] = __float2half(0.f);
        g_buf2[(size_t)b * NN * HH + h] = __float2half(0.f);
    }
}

// ---------------- transpose node_feats [B,C,N] -> fp16 [B,N,C] ---------------------
__global__ void k_transpose(const float* __restrict__ x) {
    __shared__ float tile[32][33];
    int b  = blockIdx.z;
    int n0 = blockIdx.x * 32;
    int c0 = blockIdx.y * 32;
    int tx = threadIdx.x, ty = threadIdx.y;
    tile[ty][tx] = x[((size_t)b * CC + c0 + ty) * NN + n0 + tx];
    __syncthreads();
    g_xtH[((size_t)b * NN + n0 + ty) * CC + c0 + tx] = __float2half(tile[tx][ty]);
}

// ---------------- pack weights -----------------------------------------------------
__global__ void k_pack(const float* __restrict__ w1c, const float* __restrict__ w2c,
                       const float* __restrict__ wm, const float* __restrict__ wm2) {
    int t = blockIdx.x * blockDim.x + threadIdx.x;
    int stride = gridDim.x * blockDim.x;
    for (int e = t; e < HH * KTOT; e += stride) {
        int h = e / KTOT, k = e % KTOT;
        float w;
        if (k < 192)      { int j = k / 64,  c = k % 64;            w = w1c[(h * CC + c) * 3 + j]; }
        else if (k < 960) { int kk = k - 192; int j = kk / 256, c = kk % 256; w = w2c[(h * HH + c) * 3 + j]; }
        else              { int kk = k - 960; w = wm[kk * HH + h]; }
        g_wpHi[e] = __float2half(w);
    }
    for (int e = t; e < PP * HH; e += stride) {
        int p = e >> 8, k = e & 255;
        float w = wm2[k * PP + p];
        __half hi = __float2half(w);
        g_w2Hi[e] = hi;
        g_w2Lo[e] = __float2half(w - __half2float(hi));
    }
}

// ---------------- unified gather + mma.sync GEMM (KC=64, 64x64 warp tiles) ---------
// STAGE 0: conv1 src=g_xtH (K=192, cp.async gather)            -> g_buf1 + stats0
// STAGE 1: conv2 src=g_buf1 (K=768, gather + h2 sub/relu)      -> g_buf2 + stats1
// STAGE 2: mlp1  src=g_buf2 (K=320: 256 h2 sub/relu, 64 z*sd)  -> relu -> g_buf1
// Norm scale istd folded into epilogue: o = istd*acc + bias.
// CTA 128 thr (4 warps, grid 2M x 2N, warp tile 64x64), CTA tile 128M x 128N.
template <int STAGE>
__global__ void __launch_bounds__(128, 2) k_gemm(const float* __restrict__ bias,
                                                 const int* __restrict__ children) {
    extern __shared__ __align__(16) char smem[];
    constexpr int NCH   = (STAGE == 0) ? 3 : (STAGE == 1) ? 12 : 5;
    constexpr int KBASE = (STAGE == 0) ? 0 : (STAGE == 1) ? 192 : 960;

    const int tile = blockIdx.x, hb = blockIdx.y, b = blockIdx.z;
    const int h0   = hb * 128;
    const int nbase = (STAGE == 2) ? tile * 128 : 1 + tile * 128;
    const int tid = threadIdx.x, lane = tid & 31, wid = tid >> 5;
    const int wm = wid & 1, wn = wid >> 1;
    const uint32_t sb = smem_u32(smem);
    int* sidx = (int*)(smem + GBSIDX);

    float mean = 0.f, istd = 1.f;
    if (STAGE >= 1) { mean = g_norm[STAGE - 1][b][0]; istd = g_norm[STAGE - 1][b][1]; }
    const __half2 m2    = __float2half2_rn(mean);
    const __half2 zero2 = __float2half2_rn(0.f);

    ((float*)(smem + GBBIAS))[tid] = bias[h0 + tid];
    if (STAGE < 2) {
        for (int i = tid; i < 384; i += 128) {
            int gn = nbase + i / 3;
            sidx[i] = (gn <= NREAL) ? children[b * 3 * NREAL + (gn - 1) * 3 + (i % 3)] : 0;
        }
    }
    __syncthreads();

    const __half* srcb = ((STAGE == 1) ? g_buf1 : g_buf2) + (size_t)b * NN * HH;
    const __half* xtb  = g_xtH + (size_t)b * NN * CC;
    const int m = tid;   // one full 128B row per thread

    float acc[4][8][4];
#pragma unroll
    for (int mt = 0; mt < 4; mt++)
#pragma unroll
        for (int nt = 0; nt < 8; nt++)
#pragma unroll
            for (int q = 0; q < 4; q++) acc[mt][nt][q] = 0.f;

    auto copyB = [&](int qc, int st) {
        const int kofs = KBASE + qc * 64;
        const __half* src = g_wpHi + (size_t)(h0 + m) * KTOT + kofs;
        uint32_t dst = sb + GBB_OFF + (uint32_t)st * 18432u + (uint32_t)m * 144u;
#pragma unroll
        for (int u = 0; u < 8; u++)
            cp16(dst + u * 16u, src + u * 8);
    };
    // STAGE 0: pure cp.async A gather
    auto copyA0 = [&](int qc, int st) {
        int idx = sidx[m * 3 + qc];
        const __half* src = xtb + (size_t)idx * CC;
        uint32_t dst = sb + GBA_OFF + (uint32_t)st * 18432u + (uint32_t)m * 144u;
#pragma unroll
        for (int u = 0; u < 8; u++)
            cp16(dst + u * 16u, src + u * 8);
    };
    // STAGES 1,2: gather + half2 sub/relu (scale folded into epilogue)
    auto loadA = [&](int qc, uint32_t* v) {
        if (STAGE == 2 && qc == 4) {
            const uint4* zp = (const uint4*)(g_zs + b * LL);   // 64 halfs = 8 uint4
#pragma unroll
            for (int u = 0; u < 8; u++) {
                uint4 q4 = zp[u];
                v[u * 4 + 0] = q4.x; v[u * 4 + 1] = q4.y;
                v[u * 4 + 2] = q4.z; v[u * 4 + 3] = q4.w;
            }
        } else {
            int row, c0;
            if (STAGE == 1) { int j = qc >> 2; c0 = (qc & 3) * 64; row = sidx[m * 3 + j]; }
            else            { c0 = qc * 64; row = nbase + m; }
            const uint4* p = (const uint4*)(srcb + (size_t)row * HH + c0);
#pragma unroll
            for (int u = 0; u < 8; u++) {
                uint4 q4 = p[u];
                const uint32_t* w = (const uint32_t*)&q4;
#pragma unroll
                for (int e = 0; e < 4; e++) {
                    __half2 t = *(const __half2*)&w[e];
                    t = __hmax2(__hsub2(t, m2), zero2);
                    v[u * 4 + e] = *(uint32_t*)&t;
                }
            }
        }
    };
    auto stsA = [&](const uint32_t* v, int st) {
        char* a = smem + GBA_OFF + st * 18432 + m * 144;
#pragma unroll
        for (int u = 0; u < 8; u++)
            *(uint4*)(a + u * 16) = make_uint4(v[u * 4], v[u * 4 + 1], v[u * 4 + 2], v[u * 4 + 3]);
    };

    // ---- prologue ----
    uint32_t areg[32];
    copyB(0, 0);
    if (STAGE == 0) {
        copyA0(0, 0);
        CP_COMMIT();
    } else {
        CP_COMMIT();
        loadA(0, areg);
        stsA(areg, 0);
    }
    CP_WAIT0();
    __syncthreads();

    // ---- main loop ----
    for (int qc = 0; qc < NCH; ++qc) {
        const int cst = qc & 1, nst = cst ^ 1;
        const bool more = (qc + 1 < NCH);
        if (more) {
            copyB(qc + 1, nst);
            if (STAGE == 0) copyA0(qc + 1, nst);
            CP_COMMIT();
            if (STAGE != 0) loadA(qc + 1, areg);
        }
        const uint32_t aB = sb + GBA_OFF + (uint32_t)cst * 18432u;
        const uint32_t bB = sb + GBB_OFF + (uint32_t)cst * 18432u;
#pragma unroll
        for (int s = 0; s < 4; s++) {
            const uint32_t colB = (uint32_t)(s * 16 + (lane >> 4) * 8) * 2u;
            uint32_t af[4][4];
            const uint32_t arow = (uint32_t)(wm * 64 + (lane & 15)) * 144u;
#pragma unroll
            for (int mt = 0; mt < 4; mt++)
                ldm4(af[mt], aB + arow + (uint32_t)mt * (16 * 144) + colB);
#pragma unroll
            for (int ng = 0; ng < 4; ng++) {
                uint32_t rb[4];
                const uint32_t brow = (uint32_t)(wn * 64 + ng * 16 + (lane & 15)) * 144u;
                ldm4(rb, bB + brow + colB);
#pragma unroll
                for (int mt = 0; mt < 4; mt++) {
                    mma16816(acc[mt][ng * 2 + 0], af[mt], rb[0], rb[2]);
                    mma16816(acc[mt][ng * 2 + 1], af[mt], rb[1], rb[3]);
                }
            }
        }
        if (more && STAGE != 0) stsA(areg, nst);
        CP_WAIT0();
        __syncthreads();
    }

    // ---- epilogue: o = istd*acc + bias (+relu), fp16 store, stats ----
    __half* dst = (STAGE == 1) ? g_buf2 : g_buf1;
    const float* sBias = (const float*)(smem + GBBIAS);
    float s = 0.f, ss = 0.f;
#pragma unroll
    for (int mt = 0; mt < 4; mt++) {
#pragma unroll
        for (int hr = 0; hr < 2; hr++) {
            int rrow = wm * 64 + mt * 16 + (lane >> 2) + hr * 8;
            int gn   = nbase + rrow;
            bool valid = (STAGE == 2) || (gn <= NREAL);
            if (valid) {
                __half* drow = dst + ((size_t)b * NN + gn) * HH + h0;
#pragma unroll
                for (int nt = 0; nt < 8; nt++) {
                    int col = wn * 64 + nt * 8 + (lane & 3) * 2;
                    float o0 = fmaf(acc[mt][nt][hr * 2 + 0], istd, sBias[col]);
                    float o1 = fmaf(acc[mt][nt][hr * 2 + 1], istd, sBias[col + 1]);
                    if (STAGE == 2) { o0 = fmaxf(o0, 0.f); o1 = fmaxf(o1, 0.f); }
                    *(uint32_t*)&drow[col] = pkf(o0, o1);
                    if (STAGE != 2) { s += o0 + o1; ss += o0 * o0 + o1 * o1; }
                }
            }
        }
    }
    if (STAGE != 2) {
#pragma unroll
        for (int off = 16; off > 0; off >>= 1) {
            s  += __shfl_down_sync(0xffffffffu, s,  off);
            ss += __shfl_down_sync(0xffffffffu, ss, off);
        }
        float* rs  = (float*)(smem + GBRS);
        float* rss = (float*)(smem + GBRSS);
        if (lane == 0) { rs[wid] = s; rss[wid] = ss; }
        __syncthreads();
        if (tid == 0) {
            float S = 0.f, SS = 0.f;
#pragma unroll
            for (int w = 0; w < 4; w++) { S += rs[w]; SS += rss[w]; }
            atomicAdd(&g_stats[STAGE][b][0], (double)S);
            atomicAdd(&g_stats[STAGE][b][1], (double)SS);
        }
    }
}

// ---------------- finalize norm stats (+ z*sd for stage 1) -------------------------
__global__ void k_finalize(int stage, const float* __restrict__ z) {
    int b = threadIdx.x;
    if (b < BB) {
        double s  = g_stats[stage][b][0];
        double ss = g_stats[stage][b][1];
        const double cnt = (double)HH * (double)NN;
        double mean = s / cnt;
        double var  = (ss - s * s / cnt) / (cnt - 1.0);
        if (var < 0.0) var = 0.0;
        double sd = sqrt(var) + 1e-5;
        g_norm[stage][b][0] = (float)mean;
        g_norm[stage][b][1] = (float)(1.0 / sd);
        if (stage == 1) {
            float sdf = (float)sd;
            for (int l = 0; l < LL; l++)
                g_zs[b * LL + l] = __float2half(z[b * LL + l] * sdf);
        }
    }
}

// ---------------- MLP layer 2 via mma (fp16 A via cp.async, B hi/lo) --------------
__global__ void __launch_bounds__(256, 2) k_mlp2(const float* __restrict__ b2,
                                                 float* __restrict__ out) {
    extern __shared__ __align__(16) char smem[];
    const int b   = blockIdx.y;
    const int n0  = blockIdx.x * 128;
    const int tid = threadIdx.x, lane = tid & 31, wid = tid >> 5;
    const uint32_t sb = smem_u32(smem);

#pragma unroll
    for (int pl = 0; pl < 2; ++pl) {
        const __half* gw = (pl ? g_w2Lo : g_w2Hi);
        char* dbase = smem + M2W_OFF + pl * 16896;
#pragma unroll
        for (int u = 0; u < 4; ++u) {
            int seg = tid + u * 256;
            int row = seg >> 5, s16 = seg & 31;
            *(uint4*)(dbase + row * 528 + s16 * 16) = *(const uint4*)(gw + row * 256 + s16 * 8);
        }
    }

    const __half* srcb = g_buf1 + ((size_t)b * NN + n0) * HH;
    const int r = tid >> 1, sg2 = (tid & 1) * 2;

    float acc[4][4];
#pragma unroll
    for (int nt = 0; nt < 4; nt++)
#pragma unroll
        for (int q = 0; q < 4; q++) acc[nt][q] = 0.f;

    auto copyA = [&](int qc, int st) {
        const __half* src = srcb + (size_t)r * HH + qc * 32 + sg2 * 8;
        uint32_t dst = sb + M2A_OFF + (uint32_t)st * 10240u + (uint32_t)r * 80u + (uint32_t)sg2 * 16u;
        cp16(dst, src);
        cp16(dst + 16, src + 8);
    };

    copyA(0, 0);
    CP_COMMIT();
    CP_WAIT0();
    __syncthreads();

    const uint32_t w2H = sb + M2W_OFF;
    const uint32_t w2L = w2H + 16896u;

#pragma unroll 2
    for (int qc = 0; qc < 8; ++qc) {
        const int cst = qc & 1, nst = cst ^ 1;
        const bool more = (qc + 1 < 8);
        if (more) { copyA(qc + 1, nst); CP_COMMIT(); }
        const uint32_t aB = sb + M2A_OFF + (uint32_t)cst * 10240u;
#pragma unroll
        for (int s = 0; s < 2; s++) {
            const uint32_t colB = (uint32_t)(s * 16 + (lane >> 4) * 8) * 2u;
            const uint32_t arow = (uint32_t)(wid * 16 + (lane & 15)) * 80u;
            uint32_t af[4];
            ldm4(af, aB + arow + colB);
            const uint32_t kbyte = (uint32_t)(qc * 32) * 2u + colB;
#pragma unroll
            for (int ng = 0; ng < 2; ng++) {
                const uint32_t brow = (uint32_t)(ng * 16 + (lane & 15)) * 528u;
                uint32_t rh[4], rl[4];
                ldm4(rh, w2H + brow + kbyte);
                ldm4(rl, w2L + brow + kbyte);
                mma16816(acc[ng * 2],     af, rh[0], rh[2]);
                mma16816(acc[ng * 2],     af, rl[0], rl[2]);
                mma16816(acc[ng * 2 + 1], af, rh[1], rh[3]);
                mma16816(acc[ng * 2 + 1], af, rl[1], rl[3]);
            }
        }
        CP_WAIT0();
        __syncthreads();
    }

#pragma unroll
    for (int hr = 0; hr < 2; hr++) {
        int row = wid * 16 + (lane >> 2) + hr * 8;
#pragma unroll
        for (int nt = 0; nt < 4; nt++) {
            int col = nt * 8 + (lane & 3) * 2;
            float o0 = acc[nt][hr * 2 + 0] + b2[col];
            float o1 = acc[nt][hr * 2 + 1] + b2[col + 1];
            *(float2*)&out[((size_t)b * NN + n0 + row) * PP + col] = make_float2(o0, o1);
        }
    }
}

// ---------------- launch -----------------------------------------------------------
extern "C" void kernel_launch(void* const* d_in, const int* in_sizes, int n_in,
                              void* d_out, int out_size) {
    (void)in_sizes; (void)n_in; (void)out_size;
    const float* node_feats = (const float*)d_in[0];
    const float* z          = (const float*)d_in[1];
    const int*   children   = (const int*)  d_in[2];
    const float* conv1_w    = (const float*)d_in[3];
    const float* conv1_b    = (const float*)d_in[4];
    const float* conv2_w    = (const float*)d_in[5];
    const float* conv2_b    = (const float*)d_in[6];
    const float* mlp_w1     = (const float*)d_in[7];
    const float* mlp_b1     = (const float*)d_in[8];
    const float* mlp_w2     = (const float*)d_in[9];
    const float* mlp_b2     = (const float*)d_in[10];
    float* out = (float*)d_out;

    static bool attr_done = false;
    if (!attr_done) {
        cudaFuncSetAttribute(k_gemm<0>, cudaFuncAttributeMaxDynamicSharedMemorySize, GB_SMEM);
        cudaFuncSetAttribute(k_gemm<1>, cudaFuncAttributeMaxDynamicSharedMemorySize, GB_SMEM);
        cudaFuncSetAttribute(k_gemm<2>, cudaFuncAttributeMaxDynamicSharedMemorySize, GB_SMEM);
        cudaFuncSetAttribute(k_mlp2,    cudaFuncAttributeMaxDynamicSharedMemorySize, M2_SMEM);
        attr_done = true;
    }

    k_init<<<64, 256>>>();
    k_transpose<<<dim3(NN / 32, CC / 32, BB), dim3(32, 32)>>>(node_feats);
    k_pack<<<256, 256>>>(conv1_w, conv2_w, mlp_w1, mlp_w2);

    k_gemm<0><<<dim3(16, 2, BB), 128, GB_SMEM>>>(conv1_b, children);
    k_finalize<<<1, 64>>>(0, z);
    k_gemm<1><<<dim3(16, 2, BB), 128, GB_SMEM>>>(conv2_b, children);
    k_finalize<<<1, 64>>>(1, z);
    k_gemm<2><<<dim3(16, 2, BB), 128, GB_SMEM>>>(mlp_b1, children);

    k_mlp2<<<dim3(16, BB), 256, M2_SMEM>>>(mlp_b2, out);
}

// round 15
// speedup vs baseline: 1.8519x; 1.8519x over previous
#include <cuda_runtime.h>
#include <cuda_fp16.h>
#include <cstdint>
#include <math.h>

#define BB   64
#define CC   64
#define HH   256
#define LL   64
#define PP   32
#define NREAL 2047
#define NN   2048
#define KTOT 1280   // 192 (conv1) + 768 (conv2) + 320 (mlp1)

// ---------------- global scratch ---------------------------------------------
__device__ __align__(16) __half g_xtH [(size_t)BB * NN * CC];
__device__ __align__(16) __half g_buf1[(size_t)BB * NN * HH];
__device__ __align__(16) __half g_buf2[(size_t)BB * NN * HH];
__device__ __align__(16) __half g_wpHi[HH * KTOT];
__device__ __align__(16) __half g_w2Hi[PP * HH];
__device__ __align__(16) __half g_zs[BB * LL];        // z * sd(stage1), fp16
__device__ double g_stats[2][BB][2];
__device__ float  g_norm [2][BB][2];

// ---------------- smem layouts -------------------------------------------------
// gemm (M=128, KC=64, 2-stage): A st*18432 @0 ; B st*18432 @36864
#define GBA_OFF   0
#define GBB_OFF   36864
#define GBSIDX    73728
#define GBRS      75264
#define GBRSS     75328
#define GBBIAS    75392
#define GB_SMEM   75904
// mlp2: A 2 stages @0; W2 plane @20480 (pitch 528B)
#define M2A_OFF  0
#define M2W_OFF  20480
#define M2_SMEM  37376

// ---------------- helpers -------------------------------------------------------
__device__ __forceinline__ uint32_t smem_u32(const void* p) {
    uint32_t a;
    asm("{ .reg .u64 t; cvta.to.shared.u64 t, %1; cvt.u32.u64 %0, t; }" : "=r"(a) : "l"(p));
    return a;
}
__device__ __forceinline__ void ldm4(uint32_t* r, uint32_t addr) {
    asm volatile("ldmatrix.sync.aligned.m8n8.x4.shared.b16 {%0,%1,%2,%3}, [%4];"
                 : "=r"(r[0]), "=r"(r[1]), "=r"(r[2]), "=r"(r[3]) : "r"(addr));
}
__device__ __forceinline__ void mma16816(float* c, const uint32_t* a, uint32_t b0, uint32_t b1) {
    asm volatile("mma.sync.aligned.m16n8k16.row.col.f32.f16.f16.f32 "
                 "{%0,%1,%2,%3}, {%4,%5,%6,%7}, {%8,%9}, {%0,%1,%2,%3};"
                 : "+f"(c[0]), "+f"(c[1]), "+f"(c[2]), "+f"(c[3])
                 : "r"(a[0]), "r"(a[1]), "r"(a[2]), "r"(a[3]), "r"(b0), "r"(b1));
}
__device__ __forceinline__ void cp16(uint32_t dst, const void* src) {
    asm volatile("cp.async.cg.shared.global [%0], [%1], 16;" :: "r"(dst), "l"(src));
}
#define CP_COMMIT() asm volatile("cp.async.commit_group;" ::: "memory")
#define CP_WAIT0()  asm volatile("cp.async.wait_group 0;"  ::: "memory")
__device__ __forceinline__ uint32_t pkh(__half a, __half b) {
    return (uint32_t)__half_as_ushort(a) | ((uint32_t)__half_as_ushort(b) << 16);
}
__device__ __forceinline__ uint32_t pkf(float a, float b) {
    return pkh(__float2half(a), __float2half(b));
}

// ---------------- transpose node_feats [B,C,N] -> fp16 [B,N,C] ---------------------
__global__ void k_transpose(const float* __restrict__ x) {
    __shared__ float tile[32][33];
    int b  = blockIdx.z;
    int n0 = blockIdx.x * 32;
    int c0 = blockIdx.y * 32;
    int tx = threadIdx.x, ty = threadIdx.y;
    tile[ty][tx] = x[((size_t)b * CC + c0 + ty) * NN + n0 + tx];
    __syncthreads();
    g_xtH[((size_t)b * NN + n0 + ty) * CC + c0 + tx] = __float2half(tile[tx][ty]);
}

// ---------------- pack weights + init (stats zero, node-0 rows) --------------------
__global__ void k_pack(const float* __restrict__ w1c, const float* __restrict__ w2c,
                       const float* __restrict__ wm, const float* __restrict__ wm2) {
    int t = blockIdx.x * blockDim.x + threadIdx.x;
    int stride = gridDim.x * blockDim.x;
    if (t < 2 * BB * 2) ((double*)g_stats)[t] = 0.0;
    for (int i = t; i < BB * HH; i += stride) {
        int b = i >> 8, h = i & 255;
        g_buf1[(size_t)b * NN * HH + h] = __float2half(0.f);
        g_buf2[(size_t)b * NN * HH + h] = __float2half(0.f);
    }
    for (int e = t; e < HH * KTOT; e += stride) {
        int h = e / KTOT, k = e % KTOT;
        float w;
        if (k < 192)      { int j = k / 64,  c = k % 64;            w = w1c[(h * CC + c) * 3 + j]; }
        else if (k < 960) { int kk = k - 192; int j = kk / 256, c = kk % 256; w = w2c[(h * HH + c) * 3 + j]; }
        else              { int kk = k - 960; w = wm[kk * HH + h]; }
        g_wpHi[e] = __float2half(w);
    }
    for (int e = t; e < PP * HH; e += stride) {
        int p = e >> 8, k = e & 255;
        g_w2Hi[e] = __float2half(wm2[k * PP + p]);
    }
}

// ---------------- unified gather + mma.sync GEMM (KC=64, single-plane B) -----------
// STAGE 0: conv1 src=g_xtH (K=192, cp.async gather)            -> g_buf1 + stats0
// STAGE 1: conv2 src=g_buf1 (K=768, gather + h2 sub/relu)      -> g_buf2 + stats1
// STAGE 2: mlp1  src=g_buf2 (K=320: 256 h2 sub/relu, 64 z*sd)  -> relu -> g_buf1
// Norm scale istd folded into epilogue: o = istd*acc + bias.
// CTA 256 thr, tile 128M x 128N, warp grid 2M x 4N (warp tile 64x32).
template <int STAGE>
__global__ void __launch_bounds__(256, 2) k_gemm(const float* __restrict__ bias,
                                                 const int* __restrict__ children) {
    extern __shared__ __align__(16) char smem[];
    constexpr int NCH   = (STAGE == 0) ? 3 : (STAGE == 1) ? 12 : 5;
    constexpr int KBASE = (STAGE == 0) ? 0 : (STAGE == 1) ? 192 : 960;

    const int tile = blockIdx.x, hb = blockIdx.y, b = blockIdx.z;
    const int h0   = hb * 128;
    const int nbase = (STAGE == 2) ? tile * 128 : 1 + tile * 128;
    const int tid = threadIdx.x, lane = tid & 31, wid = tid >> 5;
    const int wm = wid & 1, wn = wid >> 1;
    const uint32_t sb = smem_u32(smem);
    int* sidx = (int*)(smem + GBSIDX);

    float mean = 0.f, istd = 1.f;
    if (STAGE >= 1) { mean = g_norm[STAGE - 1][b][0]; istd = g_norm[STAGE - 1][b][1]; }
    const __half2 m2    = __float2half2_rn(mean);
    const __half2 zero2 = __float2half2_rn(0.f);

    if (tid < 128) ((float*)(smem + GBBIAS))[tid] = bias[h0 + tid];
    if (STAGE < 2) {
        for (int i = tid; i < 384; i += 256) {
            int gn = nbase + i / 3;
            sidx[i] = (gn <= NREAL) ? children[b * 3 * NREAL + (gn - 1) * 3 + (i % 3)] : 0;
        }
    }
    __syncthreads();

    const __half* srcb = ((STAGE == 1) ? g_buf1 : g_buf2) + (size_t)b * NN * HH;
    const __half* xtb  = g_xtH + (size_t)b * NN * CC;
    const int m = tid >> 1, half_ = tid & 1;

    float acc[4][4][4];
#pragma unroll
    for (int mt = 0; mt < 4; mt++)
#pragma unroll
        for (int nt = 0; nt < 4; nt++)
#pragma unroll
            for (int q = 0; q < 4; q++) acc[mt][nt][q] = 0.f;

    auto copyB = [&](int qc, int st) {
        const int kofs = KBASE + qc * 64;
        const int row = tid >> 1, sec = tid & 1;
        const __half* src = g_wpHi + (size_t)(h0 + row) * KTOT + kofs + sec * 32;
        uint32_t dst = sb + GBB_OFF + (uint32_t)st * 18432u + (uint32_t)row * 144u + (uint32_t)sec * 64u;
        cp16(dst,      src);
        cp16(dst + 16, src + 8);
        cp16(dst + 32, src + 16);
        cp16(dst + 48, src + 24);
    };
    // STAGE 0: pure cp.async A gather
    auto copyA0 = [&](int qc, int st) {
        int idx = sidx[m * 3 + qc];
        const __half* src = xtb + (size_t)idx * CC + half_ * 32;
        uint32_t dst = sb + GBA_OFF + (uint32_t)st * 18432u + (uint32_t)m * 144u + (uint32_t)half_ * 64u;
        cp16(dst,      src);
        cp16(dst + 16, src + 8);
        cp16(dst + 32, src + 16);
        cp16(dst + 48, src + 24);
    };
    // STAGES 1,2: gather + half2 sub/relu (scale folded into epilogue)
    auto loadA = [&](int qc, uint32_t* v) {
        if (STAGE == 2 && qc == 4) {
            const uint4* zp = (const uint4*)(g_zs + b * LL + half_ * 32);
#pragma unroll
            for (int u = 0; u < 4; u++) {
                uint4 q4 = zp[u];
                v[u * 4 + 0] = q4.x; v[u * 4 + 1] = q4.y;
                v[u * 4 + 2] = q4.z; v[u * 4 + 3] = q4.w;
            }
        } else {
            int row, c0;
            if (STAGE == 1) { int j = qc >> 2; c0 = (qc & 3) * 64; row = sidx[m * 3 + j]; }
            else            { c0 = qc * 64; row = nbase + m; }
            const uint4* p = (const uint4*)(srcb + (size_t)row * HH + c0 + half_ * 32);
#pragma unroll
            for (int u = 0; u < 4; u++) {
                uint4 q4 = p[u];
                const uint32_t* w = (const uint32_t*)&q4;
#pragma unroll
                for (int e = 0; e < 4; e++) {
                    __half2 t = *(const __half2*)&w[e];
                    t = __hmax2(__hsub2(t, m2), zero2);
                    v[u * 4 + e] = *(uint32_t*)&t;
                }
            }
        }
    };
    auto stsA = [&](const uint32_t* v, int st) {
        char* a = smem + GBA_OFF + st * 18432 + m * 144 + half_ * 64;
        *(uint4*)(a)      = make_uint4(v[0],  v[1],  v[2],  v[3]);
        *(uint4*)(a + 16) = make_uint4(v[4],  v[5],  v[6],  v[7]);
        *(uint4*)(a + 32) = make_uint4(v[8],  v[9],  v[10], v[11]);
        *(uint4*)(a + 48) = make_uint4(v[12], v[13], v[14], v[15]);
    };

    // ---- prologue ----
    uint32_t areg[16];
    copyB(0, 0);
    if (STAGE == 0) {
        copyA0(0, 0);
        CP_COMMIT();
    } else {
        CP_COMMIT();
        loadA(0, areg);
        stsA(areg, 0);
    }
    CP_WAIT0();
    __syncthreads();

    // ---- main loop ----
#pragma unroll 2
    for (int qc = 0; qc < NCH; ++qc) {
        const int cst = qc & 1, nst = cst ^ 1;
        const bool more = (qc + 1 < NCH);
        if (more) {
            copyB(qc + 1, nst);
            if (STAGE == 0) copyA0(qc + 1, nst);
            CP_COMMIT();
            if (STAGE != 0) loadA(qc + 1, areg);
        }
        const uint32_t aB = sb + GBA_OFF + (uint32_t)cst * 18432u;
        const uint32_t bB = sb + GBB_OFF + (uint32_t)cst * 18432u;
#pragma unroll
        for (int s = 0; s < 4; s++) {
            const uint32_t colB = (uint32_t)(s * 16 + (lane >> 4) * 8) * 2u;
            uint32_t af[4][4];
            const uint32_t arow = (uint32_t)(wm * 64 + (lane & 15)) * 144u;
#pragma unroll
            for (int mt = 0; mt < 4; mt++)
                ldm4(af[mt], aB + arow + (uint32_t)mt * (16 * 144) + colB);
#pragma unroll
            for (int ng = 0; ng < 2; ng++) {
                uint32_t rb[4];
                const uint32_t brow = (uint32_t)(wn * 32 + ng * 16 + (lane & 15)) * 144u;
                ldm4(rb, bB + brow + colB);
#pragma unroll
                for (int mt = 0; mt < 4; mt++) {
                    mma16816(acc[mt][ng * 2 + 0], af[mt], rb[0], rb[2]);
                    mma16816(acc[mt][ng * 2 + 1], af[mt], rb[1], rb[3]);
                }
            }
        }
        if (more && STAGE != 0) stsA(areg, nst);
        CP_WAIT0();
        __syncthreads();
    }

    // ---- epilogue: o = istd*acc + bias (+relu), fp16 store, stats ----
    __half* dst = (STAGE == 1) ? g_buf2 : g_buf1;
    const float* sBias = (const float*)(smem + GBBIAS);
    float s = 0.f, ss = 0.f;
#pragma unroll
    for (int mt = 0; mt < 4; mt++) {
#pragma unroll
        for (int hr = 0; hr < 2; hr++) {
            int rrow = wm * 64 + mt * 16 + (lane >> 2) + hr * 8;
            int gn   = nbase + rrow;
            bool valid = (STAGE == 2) || (gn <= NREAL);
            if (valid) {
                __half* drow = dst + ((size_t)b * NN + gn) * HH + h0;
#pragma unroll
                for (int nt = 0; nt < 4; nt++) {
                    int col = wn * 32 + nt * 8 + (lane & 3) * 2;
                    float o0 = fmaf(acc[mt][nt][hr * 2 + 0], istd, sBias[col]);
                    float o1 = fmaf(acc[mt][nt][hr * 2 + 1], istd, sBias[col + 1]);
                    if (STAGE == 2) { o0 = fmaxf(o0, 0.f); o1 = fmaxf(o1, 0.f); }
                    *(uint32_t*)&drow[col] = pkf(o0, o1);
                    if (STAGE != 2) { s += o0 + o1; ss += o0 * o0 + o1 * o1; }
                }
            }
        }
    }
    if (STAGE != 2) {
#pragma unroll
        for (int off = 16; off > 0; off >>= 1) {
            s  += __shfl_down_sync(0xffffffffu, s,  off);
            ss += __shfl_down_sync(0xffffffffu, ss, off);
        }
        float* rs  = (float*)(smem + GBRS);
        float* rss = (float*)(smem + GBRSS);
        if (lane == 0) { rs[wid] = s; rss[wid] = ss; }
        __syncthreads();
        if (tid == 0) {
            float S = 0.f, SS = 0.f;
#pragma unroll
            for (int w = 0; w < 8; w++) { S += rs[w]; SS += rss[w]; }
            atomicAdd(&g_stats[STAGE][b][0], (double)S);
            atomicAdd(&g_stats[STAGE][b][1], (double)SS);
        }
    }
}

// ---------------- finalize norm stats (+ z*sd for stage 1) -------------------------
__global__ void k_finalize(int stage, const float* __restrict__ z) {
    int b = threadIdx.x;
    if (b < BB) {
        double s  = g_stats[stage][b][0];
        double ss = g_stats[stage][b][1];
        const double cnt = (double)HH * (double)NN;
        double mean = s / cnt;
        double var  = (ss - s * s / cnt) / (cnt - 1.0);
        if (var < 0.0) var = 0.0;
        double sd = sqrt(var) + 1e-5;
        g_norm[stage][b][0] = (float)mean;
        g_norm[stage][b][1] = (float)(1.0 / sd);
        if (stage == 1) {
            float sdf = (float)sd;
            for (int l = 0; l < LL; l++)
                g_zs[b * LL + l] = __float2half(z[b * LL + l] * sdf);
        }
    }
}

// ---------------- MLP layer 2 via mma (fp16 A via cp.async, single-plane W2) -------
__global__ void __launch_bounds__(256, 2) k_mlp2(const float* __restrict__ b2,
                                                 float* __restrict__ out) {
    extern __shared__ __align__(16) char smem[];
    const int b   = blockIdx.y;
    const int n0  = blockIdx.x * 128;
    const int tid = threadIdx.x, lane = tid & 31, wid = tid >> 5;
    const uint32_t sb = smem_u32(smem);

    // load W2 plane: [32 p][256 k], pitch 528 B
    {
        char* dbase = smem + M2W_OFF;
#pragma unroll
        for (int u = 0; u < 4; ++u) {
            int seg = tid + u * 256;
            int row = seg >> 5, s16 = seg & 31;
            *(uint4*)(dbase + row * 528 + s16 * 16) = *(const uint4*)(g_w2Hi + row * 256 + s16 * 8);
        }
    }

    const __half* srcb = g_buf1 + ((size_t)b * NN + n0) * HH;
    const int r = tid >> 1, sg2 = (tid & 1) * 2;

    float acc[4][4];
#pragma unroll
    for (int nt = 0; nt < 4; nt++)
#pragma unroll
        for (int q = 0; q < 4; q++) acc[nt][q] = 0.f;

    auto copyA = [&](int qc, int st) {
        const __half* src = srcb + (size_t)r * HH + qc * 32 + sg2 * 8;
        uint32_t dst = sb + M2A_OFF + (uint32_t)st * 10240u + (uint32_t)r * 80u + (uint32_t)sg2 * 16u;
        cp16(dst, src);
        cp16(dst + 16, src + 8);
    };

    copyA(0, 0);
    CP_COMMIT();
    CP_WAIT0();
    __syncthreads();

    const uint32_t w2H = sb + M2W_OFF;

#pragma unroll 2
    for (int qc = 0; qc < 8; ++qc) {
        const int cst = qc & 1, nst = cst ^ 1;
        const bool more = (qc + 1 < 8);
        if (more) { copyA(qc + 1, nst); CP_COMMIT(); }
        const uint32_t aB = sb + M2A_OFF + (uint32_t)cst * 10240u;
#pragma unroll
        for (int s = 0; s < 2; s++) {
            const uint32_t colB = (uint32_t)(s * 16 + (lane >> 4) * 8) * 2u;
            const uint32_t arow = (uint32_t)(wid * 16 + (lane & 15)) * 80u;
            uint32_t af[4];
            ldm4(af, aB + arow + colB);
            const uint32_t kbyte = (uint32_t)(qc * 32) * 2u + colB;
#pragma unroll
            for (int ng = 0; ng < 2; ng++) {
                const uint32_t brow = (uint32_t)(ng * 16 + (lane & 15)) * 528u;
                uint32_t rh[4];
                ldm4(rh, w2H + brow + kbyte);
                mma16816(acc[ng * 2],     af, rh[0], rh[2]);
                mma16816(acc[ng * 2 + 1], af, rh[1], rh[3]);
            }
        }
        CP_WAIT0();
        __syncthreads();
    }

#pragma unroll
    for (int hr = 0; hr < 2; hr++) {
        int row = wid * 16 + (lane >> 2) + hr * 8;
#pragma unroll
        for (int nt = 0; nt < 4; nt++) {
            int col = nt * 8 + (lane & 3) * 2;
            float o0 = acc[nt][hr * 2 + 0] + b2[col];
            float o1 = acc[nt][hr * 2 + 1] + b2[col + 1];
            *(float2*)&out[((size_t)b * NN + n0 + row) * PP + col] = make_float2(o0, o1);
        }
    }
}

// ---------------- launch -----------------------------------------------------------
extern "C" void kernel_launch(void* const* d_in, const int* in_sizes, int n_in,
                              void* d_out, int out_size) {
    (void)in_sizes; (void)n_in; (void)out_size;
    const float* node_feats = (const float*)d_in[0];
    const float* z          = (const float*)d_in[1];
    const int*   children   = (const int*)  d_in[2];
    const float* conv1_w    = (const float*)d_in[3];
    const float* conv1_b    = (const float*)d_in[4];
    const float* conv2_w    = (const float*)d_in[5];
    const float* conv2_b    = (const float*)d_in[6];
    const float* mlp_w1     = (const float*)d_in[7];
    const float* mlp_b1     = (const float*)d_in[8];
    const float* mlp_w2     = (const float*)d_in[9];
    const float* mlp_b2     = (const float*)d_in[10];
    float* out = (float*)d_out;

    static bool attr_done = false;
    if (!attr_done) {
        cudaFuncSetAttribute(k_gemm<0>, cudaFuncAttributeMaxDynamicSharedMemorySize, GB_SMEM);
        cudaFuncSetAttribute(k_gemm<1>, cudaFuncAttributeMaxDynamicSharedMemorySize, GB_SMEM);
        cudaFuncSetAttribute(k_gemm<2>, cudaFuncAttributeMaxDynamicSharedMemorySize, GB_SMEM);
        cudaFuncSetAttribute(k_mlp2,    cudaFuncAttributeMaxDynamicSharedMemorySize, M2_SMEM);
        attr_done = true;
    }

    k_transpose<<<dim3(NN / 32, CC / 32, BB), dim3(32, 32)>>>(node_feats);
    k_pack<<<256, 256>>>(conv1_w, conv2_w, mlp_w1, mlp_w2);

    k_gemm<0><<<dim3(16, 2, BB), 256, GB_SMEM>>>(conv1_b, children);
    k_finalize<<<1, 64>>>(0, z);
    k_gemm<1><<<dim3(16, 2, BB), 256, GB_SMEM>>>(conv2_b, children);
    k_finalize<<<1, 64>>>(1, z);
    k_gemm<2><<<dim3(16, 2, BB), 256, GB_SMEM>>>(mlp_b1, children);

    k_mlp2<<<dim3(16, BB), 256, M2_SMEM>>>(mlp_b2, out);
}